// round 1
// baseline (speedup 1.0000x reference)
#include <cuda_runtime.h>
#include <math.h>
#include <stdint.h>

// ---------------- constants ----------------
#define kB 2
#define kT 1024
#define kD 1024
#define kDFF 4096
#define kV 32000
#define kL 12
#define kN (kB * kT)  // 2048 rows

// ---------------- scratch (static device allocations; no cudaMalloc) --------
__device__ float g_x[kN * kD];
__device__ float g_h[kN * kD];
__device__ float g_r[kN * kD];
__device__ float g_k[kN * kD];
__device__ float g_v[kN * kD];
__device__ float g_att[kN * kD];
__device__ float g_he[kN * kD];
__device__ float g_ff1[kN * kDFF];
__device__ float g_ff2[kN * kDFF];
__device__ float g_elog[(size_t)kN * kV];
__device__ double g_gn_sum[kB];
__device__ double g_gn_sumsq[kB];
__device__ float g_hbar[kB * kD];
__device__ float g_conf[2 * kB];
__device__ float g_lse_f[kN], g_tgt_f[kN];
__device__ int   g_amax_f[kN];
__device__ float g_lse_e[2 * kN], g_tgt_e[2 * kN], g_ent_e[2 * kN];
__device__ int   g_amax_e[2 * kN];

// ---------------- LayerNorm over rows of length kD ----------------
__device__ __forceinline__ void row_ln_body(const float* __restrict__ x,
                                            float* __restrict__ o,
                                            const float* __restrict__ w,
                                            const float* __restrict__ bb) {
  int tid = threadIdx.x;
  float s = 0.f, ss = 0.f;
  for (int i = tid; i < kD; i += blockDim.x) { float v = x[i]; s += v; ss += v * v; }
  __shared__ float shs[32], shss[32];
  for (int off = 16; off; off >>= 1) {
    s += __shfl_down_sync(0xffffffffu, s, off);
    ss += __shfl_down_sync(0xffffffffu, ss, off);
  }
  if ((tid & 31) == 0) { shs[tid >> 5] = s; shss[tid >> 5] = ss; }
  __syncthreads();
  int nw = (blockDim.x + 31) >> 5;
  if (tid < 32) {
    s = tid < nw ? shs[tid] : 0.f;
    ss = tid < nw ? shss[tid] : 0.f;
    for (int off = 16; off; off >>= 1) {
      s += __shfl_down_sync(0xffffffffu, s, off);
      ss += __shfl_down_sync(0xffffffffu, ss, off);
    }
    if (tid == 0) { shs[0] = s; shss[0] = ss; }
  }
  __syncthreads();
  float mean = shs[0] / (float)kD;
  float var = shss[0] / (float)kD - mean * mean;
  float rstd = rsqrtf(var + 1e-5f);
  for (int i = tid; i < kD; i += blockDim.x)
    o[i] = (x[i] - mean) * rstd * w[i] + bb[i];
}

__global__ void ln_rows(const float* __restrict__ in, float* __restrict__ out,
                        const float* __restrict__ w, const float* __restrict__ bb) {
  size_t row = blockIdx.x;
  row_ln_body(in + row * kD, out + row * kD, w, bb);
}

__global__ void embed_ln(const int* __restrict__ idx, const float* __restrict__ embed,
                         const float* __restrict__ w, const float* __restrict__ bb,
                         float* __restrict__ out) {
  size_t row = blockIdx.x;
  const float* x = embed + (size_t)idx[row] * kD;
  row_ln_body(x, out + row * kD, w, bb);
}

// ---------------- SGEMM: C[n,m] = sum_k A[n,k]*W[m,k] ----------------
// A: [N,K] row-major, W: [M,K] row-major. 128x128 tile, BK=8, 256 threads, 8x8/thread.
// MODE 0: store, MODE 1: sigmoid, MODE 2: add into existing C (residual).
#define GBM 128
#define GBN 128
#define GBK 8
template <int MODE>
__global__ void __launch_bounds__(256, 2)
sgemm_nt(const float* __restrict__ A, const float* __restrict__ W,
         float* __restrict__ C, int N, int M, int K) {
  __shared__ float As[GBK][GBM];
  __shared__ float Ws[GBK][GBN];
  int tid = threadIdx.x;
  int tile_n = blockIdx.x * GBM;
  int tile_m = blockIdx.y * GBN;
  int lrow = tid >> 1;            // 0..127
  int lcol = (tid & 1) * 4;       // 0 or 4
  const float* Ab = A + (size_t)(tile_n + lrow) * K + lcol;
  const float* Wb = W + (size_t)(tile_m + lrow) * K + lcol;
  int tx = tid & 15, ty = tid >> 4;
  float acc[8][8];
#pragma unroll
  for (int i = 0; i < 8; i++)
#pragma unroll
    for (int j = 0; j < 8; j++) acc[i][j] = 0.f;

  for (int k0 = 0; k0 < K; k0 += GBK) {
    float4 a4 = *(const float4*)(Ab + k0);
    float4 w4 = *(const float4*)(Wb + k0);
    As[lcol + 0][lrow] = a4.x; As[lcol + 1][lrow] = a4.y;
    As[lcol + 2][lrow] = a4.z; As[lcol + 3][lrow] = a4.w;
    Ws[lcol + 0][lrow] = w4.x; Ws[lcol + 1][lrow] = w4.y;
    Ws[lcol + 2][lrow] = w4.z; Ws[lcol + 3][lrow] = w4.w;
    __syncthreads();
#pragma unroll
    for (int kk = 0; kk < GBK; kk++) {
      float4 ra0 = *(const float4*)&As[kk][ty * 8];
      float4 ra1 = *(const float4*)&As[kk][ty * 8 + 4];
      float4 rb0 = *(const float4*)&Ws[kk][tx * 8];
      float4 rb1 = *(const float4*)&Ws[kk][tx * 8 + 4];
      float ra[8] = {ra0.x, ra0.y, ra0.z, ra0.w, ra1.x, ra1.y, ra1.z, ra1.w};
      float rb[8] = {rb0.x, rb0.y, rb0.z, rb0.w, rb1.x, rb1.y, rb1.z, rb1.w};
#pragma unroll
      for (int i = 0; i < 8; i++)
#pragma unroll
        for (int j = 0; j < 8; j++) acc[i][j] = fmaf(ra[i], rb[j], acc[i][j]);
    }
    __syncthreads();
  }
#pragma unroll
  for (int i = 0; i < 8; i++) {
    size_t row = (size_t)(tile_n + ty * 8 + i);
#pragma unroll
    for (int j = 0; j < 8; j++) {
      size_t col = (size_t)(tile_m + tx * 8 + j);
      float val = acc[i][j];
      if (MODE == 1) val = 1.f / (1.f + expf(-val));
      if (MODE == 2) val += C[row * M + col];
      C[row * M + col] = val;
    }
  }
}

// ---------------- TimeMix decay scan (replicates reference numerics) --------
__global__ void timemix(const float* __restrict__ r, const float* __restrict__ k,
                        const float* __restrict__ v, const float* __restrict__ decay_l,
                        float* __restrict__ out) {
  int gid = blockIdx.x * blockDim.x + threadIdx.x;  // 0..kB*kD-1
  int b = gid / kD, d = gid % kD;
  float dec = 1.f / (1.f + expf(-decay_l[d]));
  float logdec = logf(fmaxf(dec, 1e-7f));
  const float* kp = k + (size_t)b * kT * kD + d;
  const float* vp = v + (size_t)b * kT * kD + d;
  const float* rp = r + (size_t)b * kT * kD + d;
  float* op = out + (size_t)b * kT * kD + d;
  float cum = 0.f;
  for (int t = 0; t < kT; t++) {
    float scale = expf((float)t * logdec);
    float denom = fmaxf(scale, 1e-10f);
    float kv = kp[(size_t)t * kD] * vp[(size_t)t * kD];
    cum += kv / denom;
    op[(size_t)t * kD] = rp[(size_t)t * kD] * (cum * scale);
  }
}

// ---------------- GroupNorm(1, D) over (T,D) per batch ----------------
__global__ void gn_zero() {
  if (threadIdx.x < kB) { g_gn_sum[threadIdx.x] = 0.0; g_gn_sumsq[threadIdx.x] = 0.0; }
}

__global__ void gn_reduce(const float* __restrict__ in) {
  const int CH = 64;
  int b = blockIdx.x / CH, chunk = blockIdx.x % CH;
  const int n = kT * kD / CH;
  const float* p = in + (size_t)b * kT * kD + (size_t)chunk * n;
  double s = 0.0, ss = 0.0;
  for (int i = threadIdx.x; i < n; i += blockDim.x) {
    double v = (double)p[i];
    s += v; ss += v * v;
  }
  __shared__ double sh1[32], sh2[32];
  for (int off = 16; off; off >>= 1) {
    s += __shfl_down_sync(0xffffffffu, s, off);
    ss += __shfl_down_sync(0xffffffffu, ss, off);
  }
  int tid = threadIdx.x;
  if ((tid & 31) == 0) { sh1[tid >> 5] = s; sh2[tid >> 5] = ss; }
  __syncthreads();
  int nw = (blockDim.x + 31) >> 5;
  if (tid < 32) {
    s = tid < nw ? sh1[tid] : 0.0;
    ss = tid < nw ? sh2[tid] : 0.0;
    for (int off = 16; off; off >>= 1) {
      s += __shfl_down_sync(0xffffffffu, s, off);
      ss += __shfl_down_sync(0xffffffffu, ss, off);
    }
    if (tid == 0) { atomicAdd(&g_gn_sum[b], s); atomicAdd(&g_gn_sumsq[b], ss); }
  }
}

__global__ void gn_apply(const float* __restrict__ in, const float* __restrict__ gw,
                         const float* __restrict__ gb, float* __restrict__ out) {
  int b = blockIdx.y;
  int idx = blockIdx.x * blockDim.x + threadIdx.x;  // over T*D
  double inv = 1.0 / (double)(kT * kD);
  double m = g_gn_sum[b] * inv;
  double var = g_gn_sumsq[b] * inv - m * m;
  float rstd = rsqrtf((float)var + 1e-5f);
  float mf = (float)m;
  int d = idx & (kD - 1);
  size_t off = (size_t)b * kT * kD + idx;
  out[off] = (in[off] - mf) * rstd * gw[d] + gb[d];
}

// ---------------- SwiGLU elementwise ----------------
__global__ void silu_mul(float* __restrict__ a, const float* __restrict__ b2) {
  int i = blockIdx.x * blockDim.x + threadIdx.x;
  float av = a[i];
  float sg = 1.f / (1.f + expf(-av));
  a[i] = av * sg * b2[i];
}

// ---------------- per-row logit stats ----------------
__global__ void rowstats(const float* __restrict__ logits, const int* __restrict__ targets,
                         float* __restrict__ lse, float* __restrict__ tgt,
                         int* __restrict__ amax, float* __restrict__ ent) {
  int row = blockIdx.x;
  const float* Lp = logits + (size_t)row * kV;
  int tid = threadIdx.x;
  __shared__ float svals[256];
  __shared__ int sidx[256];
  float m = -3.4e38f; int mi = 0;
  for (int i = tid; i < kV; i += 256) {
    float v = Lp[i];
    if (v > m) { m = v; mi = i; }
  }
  svals[tid] = m; sidx[tid] = mi;
  __syncthreads();
  for (int off = 128; off > 0; off >>= 1) {
    if (tid < off) {
      float v2 = svals[tid + off]; int i2 = sidx[tid + off];
      if (v2 > svals[tid] || (v2 == svals[tid] && i2 < sidx[tid])) { svals[tid] = v2; sidx[tid] = i2; }
    }
    __syncthreads();
  }
  float M = svals[0]; int MI = sidx[0];
  __syncthreads();
  float s = 0.f, t2 = 0.f;
  for (int i = tid; i < kV; i += 256) {
    float v = Lp[i] - M;
    float e = expf(v);
    s += e; t2 += e * v;
  }
  svals[tid] = s; __syncthreads();
  for (int off = 128; off > 0; off >>= 1) { if (tid < off) svals[tid] += svals[tid + off]; __syncthreads(); }
  float S = svals[0]; __syncthreads();
  svals[tid] = t2; __syncthreads();
  for (int off = 128; off > 0; off >>= 1) { if (tid < off) svals[tid] += svals[tid + off]; __syncthreads(); }
  float T2 = svals[0];
  if (tid == 0) {
    lse[row] = M + logf(S);
    if (ent) ent[row] = logf(S) - T2 / S;
    amax[row] = MI;
    tgt[row] = Lp[targets[row]];
  }
}

// ---------------- exit gate ----------------
__global__ void colmean(const float* __restrict__ he, float* __restrict__ hbar) {
  int d = blockIdx.x * blockDim.x + threadIdx.x;
  int b = blockIdx.y;
  float s = 0.f;
  const float* p = he + (size_t)b * kT * kD + d;
  for (int t = 0; t < kT; t++) s += p[(size_t)t * kD];
  hbar[b * kD + d] = s / (float)kT;
}

__global__ void gate_kernel(const float* __restrict__ hbar, const float* __restrict__ w1,
                            const float* __restrict__ b1, const float* __restrict__ w2,
                            const float* __restrict__ b2, int j) {
  __shared__ float g[kB][64];
  int tid = threadIdx.x;
  if (tid < kB * 64) {
    int b = tid / 64, u = tid % 64;
    float s = 0.f;
    const float* hp = hbar + b * kD;
    const float* wp = w1 + (size_t)u * kD;
    for (int d = 0; d < kD; d++) s += hp[d] * wp[d];
    g[b][u] = fmaxf(s + b1[u], 0.f);
  }
  __syncthreads();
  if (tid < kB) {
    float s = 0.f;
    for (int u = 0; u < 64; u++) s += g[tid][u] * w2[u];
    g_conf[j * kB + tid] = 1.f / (1.f + expf(-(s + b2[0])));
  }
}

// ---------------- loss assembly ----------------
__global__ void loss_kernel(float* __restrict__ loss_out) {
  int tid = threadIdx.x;
  float ce_f = 0.f, ce_e[2] = {0.f, 0.f};
  float ag[2][2] = {{0.f, 0.f}, {0.f, 0.f}};
  float oc[2] = {0.f, 0.f};
  const float maxent = logf((float)kV);
  for (int r = tid; r < kN; r += 256) {
    int fp = g_amax_f[r];
    ce_f += g_lse_f[r] - g_tgt_f[r];
    int b = r / kT;
#pragma unroll
    for (int j = 0; j < 2; j++) {
      ce_e[j] += g_lse_e[j * kN + r] - g_tgt_e[j * kN + r];
      int ep = g_amax_e[j * kN + r];
      if (ep == fp) ag[j][b] += 1.f;
      else oc[j] += (1.f - g_ent_e[j * kN + r] / maxent);
    }
  }
  __shared__ float sh[256];
  float vals[9] = {ce_f, ce_e[0], ce_e[1], ag[0][0], ag[0][1], ag[1][0], ag[1][1], oc[0], oc[1]};
  float red[9];
#pragma unroll
  for (int q = 0; q < 9; q++) {
    sh[tid] = vals[q];
    __syncthreads();
    for (int off = 128; off > 0; off >>= 1) { if (tid < off) sh[tid] += sh[tid + off]; __syncthreads(); }
    red[q] = sh[0];
    __syncthreads();
  }
  if (tid == 0) {
    const float w[2] = {0.3f, 0.5f};
    float loss = red[0] / (float)kN;  // final CE * 1.0
    for (int j = 0; j < 2; j++) {
      loss += w[j] * (red[1 + j] / (float)kN);
      float bce = 0.f;
      for (int b = 0; b < kB; b++) {
        float agree = red[3 + j * 2 + b] / (float)kT;
        float c = fminf(fmaxf(g_conf[j * kB + b], 1e-7f), 1.f - 1e-7f);
        bce += -(agree * logf(c) + (1.f - agree) * logf(1.f - c));
      }
      loss += 0.5f * (bce / (float)kB);
      loss += 0.1f * (red[7 + j] / (float)kN);
    }
    loss_out[0] = loss;
  }
}

// ---------------- host orchestration ----------------
extern "C" void kernel_launch(void* const* d_in, const int* in_sizes, int n_in,
                              void* d_out, int out_size) {
  const int* idx = (const int*)d_in[0];
  const int* targets = (const int*)d_in[1];
  const float* embed = (const float*)d_in[2];
  const float* ln_in_w = (const float*)d_in[3];
  const float* ln_in_b = (const float*)d_in[4];
  const float* Wr = (const float*)d_in[5];
  const float* Wk = (const float*)d_in[6];
  const float* Wv = (const float*)d_in[7];
  const float* Wo_tm = (const float*)d_in[8];
  const float* decay = (const float*)d_in[9];
  const float* gn_w = (const float*)d_in[10];
  const float* gn_b = (const float*)d_in[11];
  const float* ln1_w = (const float*)d_in[12];
  const float* ln1_b = (const float*)d_in[13];
  const float* ln2_w = (const float*)d_in[14];
  const float* ln2_b = (const float*)d_in[15];
  const float* W1 = (const float*)d_in[16];
  const float* W2 = (const float*)d_in[17];
  const float* Wo_cm = (const float*)d_in[18];
  const float* ln_out_w = (const float*)d_in[19];
  const float* ln_out_b = (const float*)d_in[20];
  const float* exit_ln_w = (const float*)d_in[21];
  const float* exit_ln_b = (const float*)d_in[22];
  const float* exit_head = (const float*)d_in[23];
  const float* gate_w1 = (const float*)d_in[24];
  const float* gate_b1 = (const float*)d_in[25];
  const float* gate_w2 = (const float*)d_in[26];
  const float* gate_b2 = (const float*)d_in[27];
  float* out = (float*)d_out;

  float *xp, *hp, *rp, *kp, *vp, *attp, *hep, *ff1p, *ff2p, *elp, *hbarp;
  float *lse_f, *tgt_f, *lse_e, *tgt_e, *ent_e;
  int *amax_f, *amax_e;
  cudaGetSymbolAddress((void**)&xp, g_x);
  cudaGetSymbolAddress((void**)&hp, g_h);
  cudaGetSymbolAddress((void**)&rp, g_r);
  cudaGetSymbolAddress((void**)&kp, g_k);
  cudaGetSymbolAddress((void**)&vp, g_v);
  cudaGetSymbolAddress((void**)&attp, g_att);
  cudaGetSymbolAddress((void**)&hep, g_he);
  cudaGetSymbolAddress((void**)&ff1p, g_ff1);
  cudaGetSymbolAddress((void**)&ff2p, g_ff2);
  cudaGetSymbolAddress((void**)&elp, g_elog);
  cudaGetSymbolAddress((void**)&hbarp, g_hbar);
  cudaGetSymbolAddress((void**)&lse_f, g_lse_f);
  cudaGetSymbolAddress((void**)&tgt_f, g_tgt_f);
  cudaGetSymbolAddress((void**)&amax_f, g_amax_f);
  cudaGetSymbolAddress((void**)&lse_e, g_lse_e);
  cudaGetSymbolAddress((void**)&tgt_e, g_tgt_e);
  cudaGetSymbolAddress((void**)&ent_e, g_ent_e);
  cudaGetSymbolAddress((void**)&amax_e, g_amax_e);

  dim3 gemm_dd(kN / GBM, kD / GBN);     // (16, 8)
  dim3 gemm_dff(kN / GBM, kDFF / GBN);  // (16, 32)
  dim3 gemm_v(kN / GBM, kV / GBN);      // (16, 250)

  // embedding + input LN
  embed_ln<<<kN, 256>>>(idx, embed, ln_in_w, ln_in_b, xp);

  for (int i = 0; i < kL; i++) {
    const float* wr = Wr + (size_t)i * kD * kD;
    const float* wk = Wk + (size_t)i * kD * kD;
    const float* wv = Wv + (size_t)i * kD * kD;
    const float* wo = Wo_tm + (size_t)i * kD * kD;
    // --- TimeMix ---
    ln_rows<<<kN, 256>>>(xp, hp, ln1_w + i * kD, ln1_b + i * kD);
    sgemm_nt<1><<<gemm_dd, 256>>>(hp, wr, rp, kN, kD, kD);
    sgemm_nt<0><<<gemm_dd, 256>>>(hp, wk, kp, kN, kD, kD);
    sgemm_nt<0><<<gemm_dd, 256>>>(hp, wv, vp, kN, kD, kD);
    timemix<<<kB * kD / 128, 128>>>(rp, kp, vp, decay + i * kD, attp);
    gn_zero<<<1, 32>>>();
    gn_reduce<<<kB * 64, 256>>>(attp);
    gn_apply<<<dim3(kT * kD / 256, kB), 256>>>(attp, gn_w + i * kD, gn_b + i * kD, hp);
    sgemm_nt<2><<<gemm_dd, 256>>>(hp, wo, xp, kN, kD, kD);
    // --- ChannelMix ---
    ln_rows<<<kN, 256>>>(xp, hp, ln2_w + i * kD, ln2_b + i * kD);
    sgemm_nt<0><<<gemm_dff, 256>>>(hp, W1 + (size_t)i * kDFF * kD, ff1p, kN, kDFF, kD);
    sgemm_nt<0><<<gemm_dff, 256>>>(hp, W2 + (size_t)i * kDFF * kD, ff2p, kN, kDFF, kD);
    silu_mul<<<(kN * kDFF) / 256, 256>>>(ff1p, ff2p);
    sgemm_nt<2><<<gemm_dd, 256>>>(ff1p, Wo_cm + (size_t)i * kD * kDFF, xp, kN, kD, kDFF);
    // --- early exits after layers 4 and 8 ---
    if (i == 3 || i == 7) {
      int j = (i == 3) ? 0 : 1;
      ln_rows<<<kN, 256>>>(xp, hep, exit_ln_w + j * kD, exit_ln_b + j * kD);
      sgemm_nt<0><<<gemm_v, 256>>>(hep, exit_head + (size_t)j * kV * kD, elp, kN, kV, kD);
      rowstats<<<kN, 256>>>(elp, targets, lse_e + j * kN, tgt_e + j * kN,
                            amax_e + j * kN, ent_e + j * kN);
      colmean<<<dim3(kD / 256, kB), 256>>>(hep, hbarp);
      gate_kernel<<<1, 128>>>(hbarp, gate_w1 + (size_t)j * 64 * kD, gate_b1 + j * 64,
                              gate_w2 + j * 64, gate_b2 + j, j);
    }
  }

  // final LN + tied head into d_out
  ln_rows<<<kN, 256>>>(xp, hp, ln_out_w, ln_out_b);
  sgemm_nt<0><<<gemm_v, 256>>>(hp, embed, out, kN, kV, kD);
  rowstats<<<kN, 256>>>(out, targets, lse_f, tgt_f, amax_f, (float*)nullptr);
  loss_kernel<<<1, 256>>>(out + (size_t)kN * kV);
}

// round 2
// speedup vs baseline: 1.7089x; 1.7089x over previous
#include <cuda_runtime.h>
#include <cuda_bf16.h>
#include <math.h>
#include <stdint.h>

// ---------------- constants ----------------
#define kB 2
#define kT 1024
#define kD 1024
#define kDFF 4096
#define kV 32000
#define kL 12
#define kN (kB * kT)  // 2048 rows

// ---------------- scratch ----------------
__device__ float g_x[kN * kD];
__device__ float g_h[kN * kD];
__device__ float g_r[kN * kD];
__device__ float g_k[kN * kD];
__device__ float g_v[kN * kD];
__device__ float g_att[kN * kD];
__device__ float g_he[kN * kD];
__device__ float g_ff1[kN * kDFF];
__device__ float g_ff2[kN * kDFF];
__device__ float g_elog[(size_t)kN * kV];
__device__ double g_gn_sum[kB];
__device__ double g_gn_sumsq[kB];
__device__ float g_hbar[kB * kD];
__device__ float g_conf[2 * kB];
__device__ float g_lse_f[kN], g_tgt_f[kN];
__device__ int   g_amax_f[kN];
__device__ float g_lse_e[2 * kN], g_tgt_e[2 * kN], g_ent_e[2 * kN];
__device__ int   g_amax_e[2 * kN];

// ---------------- LayerNorm ----------------
__device__ __forceinline__ void row_ln_body(const float* __restrict__ x,
                                            float* __restrict__ o,
                                            const float* __restrict__ w,
                                            const float* __restrict__ bb) {
  int tid = threadIdx.x;
  float s = 0.f, ss = 0.f;
  for (int i = tid; i < kD; i += blockDim.x) { float v = x[i]; s += v; ss += v * v; }
  __shared__ float shs[32], shss[32];
  for (int off = 16; off; off >>= 1) {
    s += __shfl_down_sync(0xffffffffu, s, off);
    ss += __shfl_down_sync(0xffffffffu, ss, off);
  }
  if ((tid & 31) == 0) { shs[tid >> 5] = s; shss[tid >> 5] = ss; }
  __syncthreads();
  int nw = (blockDim.x + 31) >> 5;
  if (tid < 32) {
    s = tid < nw ? shs[tid] : 0.f;
    ss = tid < nw ? shss[tid] : 0.f;
    for (int off = 16; off; off >>= 1) {
      s += __shfl_down_sync(0xffffffffu, s, off);
      ss += __shfl_down_sync(0xffffffffu, ss, off);
    }
    if (tid == 0) { shs[0] = s; shss[0] = ss; }
  }
  __syncthreads();
  float mean = shs[0] / (float)kD;
  float var = shss[0] / (float)kD - mean * mean;
  float rstd = rsqrtf(var + 1e-5f);
  for (int i = tid; i < kD; i += blockDim.x)
    o[i] = (x[i] - mean) * rstd * w[i] + bb[i];
}

__global__ void ln_rows(const float* __restrict__ in, float* __restrict__ out,
                        const float* __restrict__ w, const float* __restrict__ bb) {
  size_t row = blockIdx.x;
  row_ln_body(in + row * kD, out + row * kD, w, bb);
}

__global__ void embed_ln(const int* __restrict__ idx, const float* __restrict__ embed,
                         const float* __restrict__ w, const float* __restrict__ bb,
                         float* __restrict__ out) {
  size_t row = blockIdx.x;
  const float* x = embed + (size_t)idx[row] * kD;
  row_ln_body(x, out + row * kD, w, bb);
}

// ---------------- bf16x3 tensor-core GEMM ----------------
// C[n,m] = sum_k A[n,k] * W[m,k]  (both row-major, K contiguous)
// CTA tile 128x128, BK=32, 8 warps of 64x32, mma.m16n8k16.bf16 with hi/lo split.
// MODE 0: store. 1: sigmoid. 2: += C. 3: C = silu(E) * acc.
#define SMPAD 40

__device__ __forceinline__ void mma16816(float* d, const uint32_t* a, const uint32_t* b) {
  asm volatile(
      "mma.sync.aligned.m16n8k16.row.col.f32.bf16.bf16.f32 "
      "{%0,%1,%2,%3}, {%4,%5,%6,%7}, {%8,%9}, {%0,%1,%2,%3};\n"
      : "+f"(d[0]), "+f"(d[1]), "+f"(d[2]), "+f"(d[3])
      : "r"(a[0]), "r"(a[1]), "r"(a[2]), "r"(a[3]), "r"(b[0]), "r"(b[1]));
}

template <int MODE>
__global__ void __launch_bounds__(256, 1)
gemm_bf16x3(const float* __restrict__ A, const float* __restrict__ W,
            float* __restrict__ C, const float* __restrict__ E,
            int N, int M, int K) {
  __shared__ __nv_bfloat16 sAh[128][SMPAD];
  __shared__ __nv_bfloat16 sAl[128][SMPAD];
  __shared__ __nv_bfloat16 sWh[128][SMPAD];
  __shared__ __nv_bfloat16 sWl[128][SMPAD];

  int tid = threadIdx.x;
  int row = tid >> 1;
  int cb = (tid & 1) * 16;
  const float* Ag = A + (size_t)(blockIdx.x * 128 + row) * K + cb;
  const float* Wg = W + (size_t)(blockIdx.y * 128 + row) * K + cb;

  int wid = tid >> 5, lane = tid & 31;
  int wm = wid >> 2, wn = wid & 3;  // 2 x 4 warp grid

  float acc[4][4][4];
#pragma unroll
  for (int i = 0; i < 4; i++)
#pragma unroll
    for (int j = 0; j < 4; j++)
#pragma unroll
      for (int q = 0; q < 4; q++) acc[i][j][q] = 0.f;

  float4 ra[4], rw[4];
#pragma unroll
  for (int q = 0; q < 4; q++) {
    ra[q] = *(const float4*)(Ag + q * 4);
    rw[q] = *(const float4*)(Wg + q * 4);
  }

  int ktiles = K / 32;
  for (int kt = 0; kt < ktiles; kt++) {
    // stage -> smem with hi/lo bf16 split
#pragma unroll
    for (int q = 0; q < 4; q++) {
      float va[4] = {ra[q].x, ra[q].y, ra[q].z, ra[q].w};
      float vw[4] = {rw[q].x, rw[q].y, rw[q].z, rw[q].w};
#pragma unroll
      for (int e = 0; e < 4; e++) {
        int c = cb + q * 4 + e;
        __nv_bfloat16 ha = __float2bfloat16(va[e]);
        sAh[row][c] = ha;
        sAl[row][c] = __float2bfloat16(va[e] - __bfloat162float(ha));
        __nv_bfloat16 hw = __float2bfloat16(vw[e]);
        sWh[row][c] = hw;
        sWl[row][c] = __float2bfloat16(vw[e] - __bfloat162float(hw));
      }
    }
    __syncthreads();
    if (kt + 1 < ktiles) {
      const float* An = Ag + (size_t)(kt + 1) * 32;
      const float* Wn = Wg + (size_t)(kt + 1) * 32;
#pragma unroll
      for (int q = 0; q < 4; q++) {
        ra[q] = *(const float4*)(An + q * 4);
        rw[q] = *(const float4*)(Wn + q * 4);
      }
    }
#pragma unroll
    for (int kk = 0; kk < 32; kk += 16) {
      uint32_t bh[4][2], bl[4][2];
      int c0 = kk + ((lane & 3) << 1);
#pragma unroll
      for (int nt = 0; nt < 4; nt++) {
        int r0 = wn * 32 + nt * 8 + (lane >> 2);
        bh[nt][0] = *(const uint32_t*)&sWh[r0][c0];
        bh[nt][1] = *(const uint32_t*)&sWh[r0][c0 + 8];
        bl[nt][0] = *(const uint32_t*)&sWl[r0][c0];
        bl[nt][1] = *(const uint32_t*)&sWl[r0][c0 + 8];
      }
#pragma unroll
      for (int mt = 0; mt < 4; mt++) {
        int r0 = wm * 64 + mt * 16 + (lane >> 2);
        uint32_t ah[4], al[4];
        ah[0] = *(const uint32_t*)&sAh[r0][c0];
        ah[1] = *(const uint32_t*)&sAh[r0 + 8][c0];
        ah[2] = *(const uint32_t*)&sAh[r0][c0 + 8];
        ah[3] = *(const uint32_t*)&sAh[r0 + 8][c0 + 8];
        al[0] = *(const uint32_t*)&sAl[r0][c0];
        al[1] = *(const uint32_t*)&sAl[r0 + 8][c0];
        al[2] = *(const uint32_t*)&sAl[r0][c0 + 8];
        al[3] = *(const uint32_t*)&sAl[r0 + 8][c0 + 8];
#pragma unroll
        for (int nt = 0; nt < 4; nt++) {
          mma16816(acc[mt][nt], ah, bh[nt]);
          mma16816(acc[mt][nt], ah, bl[nt]);
          mma16816(acc[mt][nt], al, bh[nt]);
        }
      }
    }
    __syncthreads();
  }

  // epilogue
#pragma unroll
  for (int mt = 0; mt < 4; mt++) {
#pragma unroll
    for (int nt = 0; nt < 4; nt++) {
      int r0 = blockIdx.x * 128 + wm * 64 + mt * 16 + (lane >> 2);
      int c = blockIdx.y * 128 + wn * 32 + nt * 8 + ((lane & 3) << 1);
#pragma unroll
      for (int half = 0; half < 2; half++) {
        int r = r0 + half * 8;
        size_t off = (size_t)r * M + c;
        float v0 = acc[mt][nt][half * 2 + 0];
        float v1 = acc[mt][nt][half * 2 + 1];
        if (MODE == 1) {
          v0 = 1.f / (1.f + expf(-v0));
          v1 = 1.f / (1.f + expf(-v1));
        } else if (MODE == 2) {
          float2 old = *(const float2*)&C[off];
          v0 += old.x; v1 += old.y;
        } else if (MODE == 3) {
          float2 e2 = *(const float2*)&E[off];
          v0 *= e2.x / (1.f + expf(-e2.x));
          v1 *= e2.y / (1.f + expf(-e2.y));
        }
        float2 o2 = {v0, v1};
        *(float2*)&C[off] = o2;
      }
    }
  }
}

// ---------------- TimeMix decay scan (chunked, matches reference numerics) --
#define TMCH 16
__global__ void timemix2(const float* __restrict__ r, const float* __restrict__ k,
                         const float* __restrict__ v, const float* __restrict__ decay_l,
                         float* __restrict__ out) {
  int b = blockIdx.x / (kD / 32);
  int dg = blockIdx.x % (kD / 32);
  int d = dg * 32 + threadIdx.x;
  int chunk = threadIdx.y;
  const int clen = kT / TMCH;  // 64
  int t0 = chunk * clen;

  float dec = 1.f / (1.f + expf(-decay_l[d]));
  float logdec = logf(fmaxf(dec, 1e-7f));
  size_t base = (size_t)b * kT * kD + d;

  float s = 0.f;
  for (int t = t0; t < t0 + clen; t++) {
    float scale = expf((float)t * logdec);
    float denom = fmaxf(scale, 1e-10f);
    s += k[base + (size_t)t * kD] * v[base + (size_t)t * kD] / denom;
  }
  __shared__ float cs[TMCH][32];
  cs[chunk][threadIdx.x] = s;
  __syncthreads();
  float cum = 0.f;
  for (int c = 0; c < chunk; c++) cum += cs[c][threadIdx.x];
  for (int t = t0; t < t0 + clen; t++) {
    float scale = expf((float)t * logdec);
    float denom = fmaxf(scale, 1e-10f);
    cum += k[base + (size_t)t * kD] * v[base + (size_t)t * kD] / denom;
    out[base + (size_t)t * kD] = r[base + (size_t)t * kD] * (cum * scale);
  }
}

// ---------------- GroupNorm(1,D) over (T,D) per batch ----------------
__global__ void gn_zero() {
  if (threadIdx.x < kB) { g_gn_sum[threadIdx.x] = 0.0; g_gn_sumsq[threadIdx.x] = 0.0; }
}

__global__ void gn_reduce(const float* __restrict__ in) {
  const int CH = 64;
  int b = blockIdx.x / CH, chunk = blockIdx.x % CH;
  const int n = kT * kD / CH;
  const float* p = in + (size_t)b * kT * kD + (size_t)chunk * n;
  double s = 0.0, ss = 0.0;
  for (int i = threadIdx.x; i < n; i += blockDim.x) {
    double v = (double)p[i];
    s += v; ss += v * v;
  }
  __shared__ double sh1[32], sh2[32];
  for (int off = 16; off; off >>= 1) {
    s += __shfl_down_sync(0xffffffffu, s, off);
    ss += __shfl_down_sync(0xffffffffu, ss, off);
  }
  int tid = threadIdx.x;
  if ((tid & 31) == 0) { sh1[tid >> 5] = s; sh2[tid >> 5] = ss; }
  __syncthreads();
  int nw = (blockDim.x + 31) >> 5;
  if (tid < 32) {
    s = tid < nw ? sh1[tid] : 0.0;
    ss = tid < nw ? sh2[tid] : 0.0;
    for (int off = 16; off; off >>= 1) {
      s += __shfl_down_sync(0xffffffffu, s, off);
      ss += __shfl_down_sync(0xffffffffu, ss, off);
    }
    if (tid == 0) { atomicAdd(&g_gn_sum[b], s); atomicAdd(&g_gn_sumsq[b], ss); }
  }
}

__global__ void gn_apply(const float* __restrict__ in, const float* __restrict__ gw,
                         const float* __restrict__ gb, float* __restrict__ out) {
  int b = blockIdx.y;
  int idx = blockIdx.x * blockDim.x + threadIdx.x;
  double inv = 1.0 / (double)(kT * kD);
  double m = g_gn_sum[b] * inv;
  double var = g_gn_sumsq[b] * inv - m * m;
  float rstd = rsqrtf((float)var + 1e-5f);
  float mf = (float)m;
  int d = idx & (kD - 1);
  size_t off = (size_t)b * kT * kD + idx;
  out[off] = (in[off] - mf) * rstd * gw[d] + gb[d];
}

// ---------------- per-row logit stats ----------------
__global__ void rowstats(const float* __restrict__ logits, const int* __restrict__ targets,
                         float* __restrict__ lse, float* __restrict__ tgt,
                         int* __restrict__ amax, float* __restrict__ ent) {
  int row = blockIdx.x;
  const float* Lp = logits + (size_t)row * kV;
  int tid = threadIdx.x;
  __shared__ float svals[256];
  __shared__ int sidx[256];
  float m = -3.4e38f; int mi = 0;
  for (int i = tid; i < kV; i += 256) {
    float v = Lp[i];
    if (v > m) { m = v; mi = i; }
  }
  svals[tid] = m; sidx[tid] = mi;
  __syncthreads();
  for (int off = 128; off > 0; off >>= 1) {
    if (tid < off) {
      float v2 = svals[tid + off]; int i2 = sidx[tid + off];
      if (v2 > svals[tid] || (v2 == svals[tid] && i2 < sidx[tid])) { svals[tid] = v2; sidx[tid] = i2; }
    }
    __syncthreads();
  }
  float M = svals[0]; int MI = sidx[0];
  __syncthreads();
  float s = 0.f, t2 = 0.f;
  for (int i = tid; i < kV; i += 256) {
    float v = Lp[i] - M;
    float e = expf(v);
    s += e; t2 += e * v;
  }
  svals[tid] = s; __syncthreads();
  for (int off = 128; off > 0; off >>= 1) { if (tid < off) svals[tid] += svals[tid + off]; __syncthreads(); }
  float S = svals[0]; __syncthreads();
  svals[tid] = t2; __syncthreads();
  for (int off = 128; off > 0; off >>= 1) { if (tid < off) svals[tid] += svals[tid + off]; __syncthreads(); }
  float T2 = svals[0];
  if (tid == 0) {
    lse[row] = M + logf(S);
    if (ent) ent[row] = logf(S) - T2 / S;
    amax[row] = MI;
    tgt[row] = Lp[targets[row]];
  }
}

// ---------------- exit gate ----------------
__global__ void colmean(const float* __restrict__ he, float* __restrict__ hbar) {
  int d = blockIdx.x * blockDim.x + threadIdx.x;
  int b = blockIdx.y;
  float s = 0.f;
  const float* p = he + (size_t)b * kT * kD + d;
  for (int t = 0; t < kT; t++) s += p[(size_t)t * kD];
  hbar[b * kD + d] = s / (float)kT;
}

__global__ void gate_kernel(const float* __restrict__ hbar, const float* __restrict__ w1,
                            const float* __restrict__ b1, const float* __restrict__ w2,
                            const float* __restrict__ b2, int j) {
  __shared__ float g[kB][64];
  int tid = threadIdx.x;
  if (tid < kB * 64) {
    int b = tid / 64, u = tid % 64;
    float s = 0.f;
    const float* hp = hbar + b * kD;
    const float* wp = w1 + (size_t)u * kD;
    for (int d = 0; d < kD; d++) s += hp[d] * wp[d];
    g[b][u] = fmaxf(s + b1[u], 0.f);
  }
  __syncthreads();
  if (tid < kB) {
    float s = 0.f;
    for (int u = 0; u < 64; u++) s += g[tid][u] * w2[u];
    g_conf[j * kB + tid] = 1.f / (1.f + expf(-(s + b2[0])));
  }
}

// ---------------- loss assembly ----------------
__global__ void loss_kernel(float* __restrict__ loss_out) {
  int tid = threadIdx.x;
  float ce_f = 0.f, ce_e[2] = {0.f, 0.f};
  float ag[2][2] = {{0.f, 0.f}, {0.f, 0.f}};
  float oc[2] = {0.f, 0.f};
  const float maxent = logf((float)kV);
  for (int r = tid; r < kN; r += 256) {
    int fp = g_amax_f[r];
    ce_f += g_lse_f[r] - g_tgt_f[r];
    int b = r / kT;
#pragma unroll
    for (int j = 0; j < 2; j++) {
      ce_e[j] += g_lse_e[j * kN + r] - g_tgt_e[j * kN + r];
      int ep = g_amax_e[j * kN + r];
      if (ep == fp) ag[j][b] += 1.f;
      else oc[j] += (1.f - g_ent_e[j * kN + r] / maxent);
    }
  }
  __shared__ float sh[256];
  float vals[9] = {ce_f, ce_e[0], ce_e[1], ag[0][0], ag[0][1], ag[1][0], ag[1][1], oc[0], oc[1]};
  float red[9];
#pragma unroll
  for (int q = 0; q < 9; q++) {
    sh[tid] = vals[q];
    __syncthreads();
    for (int off = 128; off > 0; off >>= 1) { if (tid < off) sh[tid] += sh[tid + off]; __syncthreads(); }
    red[q] = sh[0];
    __syncthreads();
  }
  if (tid == 0) {
    const float w[2] = {0.3f, 0.5f};
    float loss = red[0] / (float)kN;
    for (int j = 0; j < 2; j++) {
      loss += w[j] * (red[1 + j] / (float)kN);
      float bce = 0.f;
      for (int b = 0; b < kB; b++) {
        float agree = red[3 + j * 2 + b] / (float)kT;
        float c = fminf(fmaxf(g_conf[j * kB + b], 1e-7f), 1.f - 1e-7f);
        bce += -(agree * logf(c) + (1.f - agree) * logf(1.f - c));
      }
      loss += 0.5f * (bce / (float)kB);
      loss += 0.1f * (red[7 + j] / (float)kN);
    }
    loss_out[0] = loss;
  }
}

// ---------------- host orchestration ----------------
extern "C" void kernel_launch(void* const* d_in, const int* in_sizes, int n_in,
                              void* d_out, int out_size) {
  const int* idx = (const int*)d_in[0];
  const int* targets = (const int*)d_in[1];
  const float* embed = (const float*)d_in[2];
  const float* ln_in_w = (const float*)d_in[3];
  const float* ln_in_b = (const float*)d_in[4];
  const float* Wr = (const float*)d_in[5];
  const float* Wk = (const float*)d_in[6];
  const float* Wv = (const float*)d_in[7];
  const float* Wo_tm = (const float*)d_in[8];
  const float* decay = (const float*)d_in[9];
  const float* gn_w = (const float*)d_in[10];
  const float* gn_b = (const float*)d_in[11];
  const float* ln1_w = (const float*)d_in[12];
  const float* ln1_b = (const float*)d_in[13];
  const float* ln2_w = (const float*)d_in[14];
  const float* ln2_b = (const float*)d_in[15];
  const float* W1 = (const float*)d_in[16];
  const float* W2 = (const float*)d_in[17];
  const float* Wo_cm = (const float*)d_in[18];
  const float* ln_out_w = (const float*)d_in[19];
  const float* ln_out_b = (const float*)d_in[20];
  const float* exit_ln_w = (const float*)d_in[21];
  const float* exit_ln_b = (const float*)d_in[22];
  const float* exit_head = (const float*)d_in[23];
  const float* gate_w1 = (const float*)d_in[24];
  const float* gate_b1 = (const float*)d_in[25];
  const float* gate_w2 = (const float*)d_in[26];
  const float* gate_b2 = (const float*)d_in[27];
  float* out = (float*)d_out;

  float *xp, *hp, *rp, *kp, *vp, *attp, *hep, *ff1p, *ff2p, *elp, *hbarp;
  float *lse_f, *tgt_f, *lse_e, *tgt_e, *ent_e;
  int *amax_f, *amax_e;
  cudaGetSymbolAddress((void**)&xp, g_x);
  cudaGetSymbolAddress((void**)&hp, g_h);
  cudaGetSymbolAddress((void**)&rp, g_r);
  cudaGetSymbolAddress((void**)&kp, g_k);
  cudaGetSymbolAddress((void**)&vp, g_v);
  cudaGetSymbolAddress((void**)&attp, g_att);
  cudaGetSymbolAddress((void**)&hep, g_he);
  cudaGetSymbolAddress((void**)&ff1p, g_ff1);
  cudaGetSymbolAddress((void**)&ff2p, g_ff2);
  cudaGetSymbolAddress((void**)&elp, g_elog);
  cudaGetSymbolAddress((void**)&hbarp, g_hbar);
  cudaGetSymbolAddress((void**)&lse_f, g_lse_f);
  cudaGetSymbolAddress((void**)&tgt_f, g_tgt_f);
  cudaGetSymbolAddress((void**)&amax_f, g_amax_f);
  cudaGetSymbolAddress((void**)&lse_e, g_lse_e);
  cudaGetSymbolAddress((void**)&tgt_e, g_tgt_e);
  cudaGetSymbolAddress((void**)&ent_e, g_ent_e);
  cudaGetSymbolAddress((void**)&amax_e, g_amax_e);

  dim3 gemm_dd(kN / 128, kD / 128);     // (16, 8)
  dim3 gemm_dff(kN / 128, kDFF / 128);  // (16, 32)
  dim3 gemm_v(kN / 128, kV / 128);      // (16, 250)

  embed_ln<<<kN, 256>>>(idx, embed, ln_in_w, ln_in_b, xp);

  for (int i = 0; i < kL; i++) {
    const float* wr = Wr + (size_t)i * kD * kD;
    const float* wk = Wk + (size_t)i * kD * kD;
    const float* wv = Wv + (size_t)i * kD * kD;
    const float* wo = Wo_tm + (size_t)i * kD * kD;
    // --- TimeMix ---
    ln_rows<<<kN, 256>>>(xp, hp, ln1_w + i * kD, ln1_b + i * kD);
    gemm_bf16x3<1><<<gemm_dd, 256>>>(hp, wr, rp, nullptr, kN, kD, kD);
    gemm_bf16x3<0><<<gemm_dd, 256>>>(hp, wk, kp, nullptr, kN, kD, kD);
    gemm_bf16x3<0><<<gemm_dd, 256>>>(hp, wv, vp, nullptr, kN, kD, kD);
    timemix2<<<kB * (kD / 32), dim3(32, TMCH)>>>(rp, kp, vp, decay + i * kD, attp);
    gn_zero<<<1, 32>>>();
    gn_reduce<<<kB * 64, 256>>>(attp);
    gn_apply<<<dim3(kT * kD / 256, kB), 256>>>(attp, gn_w + i * kD, gn_b + i * kD, hp);
    gemm_bf16x3<2><<<gemm_dd, 256>>>(hp, wo, xp, nullptr, kN, kD, kD);
    // --- ChannelMix ---
    ln_rows<<<kN, 256>>>(xp, hp, ln2_w + i * kD, ln2_b + i * kD);
    gemm_bf16x3<0><<<gemm_dff, 256>>>(hp, W1 + (size_t)i * kDFF * kD, ff1p, nullptr, kN, kDFF, kD);
    gemm_bf16x3<3><<<gemm_dff, 256>>>(hp, W2 + (size_t)i * kDFF * kD, ff2p, ff1p, kN, kDFF, kD);
    gemm_bf16x3<2><<<gemm_dd, 256>>>(ff2p, Wo_cm + (size_t)i * kD * kDFF, xp, nullptr, kN, kD, kDFF);
    // --- early exits ---
    if (i == 3 || i == 7) {
      int j = (i == 3) ? 0 : 1;
      ln_rows<<<kN, 256>>>(xp, hep, exit_ln_w + j * kD, exit_ln_b + j * kD);
      gemm_bf16x3<0><<<gemm_v, 256>>>(hep, exit_head + (size_t)j * kV * kD, elp, nullptr, kN, kV, kD);
      rowstats<<<kN, 256>>>(elp, targets, lse_e + j * kN, tgt_e + j * kN,
                            amax_e + j * kN, ent_e + j * kN);
      colmean<<<dim3(kD / 256, kB), 256>>>(hep, hbarp);
      gate_kernel<<<1, 128>>>(hbarp, gate_w1 + (size_t)j * 64 * kD, gate_b1 + j * 64,
                              gate_w2 + j * 64, gate_b2 + j, j);
    }
  }

  // final LN + tied head into d_out
  ln_rows<<<kN, 256>>>(xp, hp, ln_out_w, ln_out_b);
  gemm_bf16x3<0><<<gemm_v, 256>>>(hp, embed, out, nullptr, kN, kV, kD);
  rowstats<<<kN, 256>>>(out, targets, lse_f, tgt_f, amax_f, (float*)nullptr);
  loss_kernel<<<1, 256>>>(out + (size_t)kN * kV);
}

// round 3
// speedup vs baseline: 3.1233x; 1.8277x over previous
#include <cuda_runtime.h>
#include <cuda_bf16.h>
#include <math.h>
#include <stdint.h>

// ---------------- constants ----------------
#define kB 2
#define kT 1024
#define kD 1024
#define kDFF 4096
#define kV 32000
#define kL 12
#define kN (kB * kT)  // 2048 rows

typedef __nv_bfloat16 bf16;

// ---------------- scratch ----------------
__device__ float g_x[kN * kD];
__device__ float g_rkv[kN * 3 * kD];
__device__ float g_att[kN * kD];
__device__ float g_ff12[kN * 2 * kDFF];
__device__ float g_elog[(size_t)kN * kV];
__device__ bf16 g_h3[kN * 3 * kD];
__device__ bf16 g_ff3[kN * 3 * kDFF];
// converted weights (K' = 3K, W-layout [hi|hi|lo])
__device__ bf16 g_Wrkv3[kL * 3 * kD * 3 * kD];         // [12][3072][3072]
__device__ bf16 g_Wotm3[kL * kD * 3 * kD];             // [12][1024][3072]
__device__ bf16 g_W123[kL * 2 * kDFF * 3 * kD];        // [12][8192][3072]
__device__ bf16 g_Wocm3[kL * kD * 3 * kDFF];           // [12][1024][12288]
__device__ bf16 g_embed3[(size_t)kV * 3 * kD];         // [32000][3072]
__device__ bf16 g_exit3[(size_t)2 * kV * 3 * kD];      // [2][32000][3072]

__device__ double g_gn_sum[kB];
__device__ double g_gn_sumsq[kB];
__device__ float g_hbar[kB * kD];
__device__ float g_conf[2 * kB];
__device__ float g_lse_f[kN], g_tgt_f[kN];
__device__ int   g_amax_f[kN];
__device__ float g_lse_e[2 * kN], g_tgt_e[2 * kN], g_ent_e[2 * kN];
__device__ int   g_amax_e[2 * kN];

// ---------------- helpers ----------------
__device__ __forceinline__ uint32_t smem_u32(const void* p) {
  return (uint32_t)__cvta_generic_to_shared(p);
}
__device__ __forceinline__ void cp16(uint32_t s, const void* g) {
  asm volatile("cp.async.ca.shared.global [%0], [%1], 16;\n" ::"r"(s), "l"(g));
}
__device__ __forceinline__ void cp_commit() { asm volatile("cp.async.commit_group;\n"); }
template <int NW>
__device__ __forceinline__ void cp_wait() { asm volatile("cp.async.wait_group %0;\n" ::"n"(NW)); }
__device__ __forceinline__ void ldm_x4(uint32_t* r, uint32_t a) {
  asm volatile("ldmatrix.sync.aligned.m8n8.x4.shared.b16 {%0,%1,%2,%3}, [%4];\n"
               : "=r"(r[0]), "=r"(r[1]), "=r"(r[2]), "=r"(r[3]) : "r"(a));
}
__device__ __forceinline__ void mma16816(float* d, const uint32_t* a, const uint32_t* b) {
  asm volatile(
      "mma.sync.aligned.m16n8k16.row.col.f32.bf16.bf16.f32 "
      "{%0,%1,%2,%3}, {%4,%5,%6,%7}, {%8,%9}, {%0,%1,%2,%3};\n"
      : "+f"(d[0]), "+f"(d[1]), "+f"(d[2]), "+f"(d[3])
      : "r"(a[0]), "r"(a[1]), "r"(a[2]), "r"(a[3]), "r"(b[0]), "r"(b[1]));
}
__device__ __forceinline__ void split_bf16(float v, bf16& h, bf16& l) {
  h = __float2bfloat16(v);
  l = __float2bfloat16(v - __bfloat162float(h));
}

// ---------------- weight conversion: fp32 [R,K] -> bf16 [R', 3K] W-layout ----
// out[orow][k]=hi, out[orow][K+k]=hi, out[orow][2K+k]=lo
__global__ void conv3w(const float* __restrict__ in, bf16* __restrict__ out,
                       int K, long total4, int srcRPL, int outRPL, int outOff) {
  long i = (long)blockIdx.x * blockDim.x + threadIdx.x;
  if (i >= total4) return;
  int K4 = K >> 2;
  long rs = i / K4;
  int c = (int)(i % K4) << 2;
  long layer = rs / srcRPL;
  int r = (int)(rs % srcRPL);
  long orow = layer * outRPL + outOff + r;
  float4 v = ((const float4*)in)[i];
  float vv[4] = {v.x, v.y, v.z, v.w};
  ushort h[4], l[4];
#pragma unroll
  for (int e = 0; e < 4; e++) {
    bf16 hb, lb;
    split_bf16(vv[e], hb, lb);
    h[e] = __bfloat16_as_ushort(hb);
    l[e] = __bfloat16_as_ushort(lb);
  }
  uint2 hp = {(uint32_t)h[0] | ((uint32_t)h[1] << 16), (uint32_t)h[2] | ((uint32_t)h[3] << 16)};
  uint2 lp = {(uint32_t)l[0] | ((uint32_t)l[1] << 16), (uint32_t)l[2] | ((uint32_t)l[3] << 16)};
  bf16* ob = out + orow * (3L * K);
  *(uint2*)(ob + c) = hp;
  *(uint2*)(ob + K + c) = hp;
  *(uint2*)(ob + 2 * K + c) = lp;
}

// ---------------- bf16 pipelined GEMM ----------------
// C[n,m] = sum_k A3[n,k]*W3[m,k], A3/W3 bf16 row-major with K' columns.
// MODE 0: store. 1: sigmoid where col<sigcut else store. 2: += C.
#define BM 128
#define BN 128
#define BK 32
#define NST 3
#define LDSB 80  // bytes per smem row (40 bf16)
#define STAGE_BYTES ((BM + BN) * LDSB)

template <int MODE>
__global__ void __launch_bounds__(256, 2)
gemm3(const bf16* __restrict__ A, const bf16* __restrict__ W,
      float* __restrict__ C, int M, int Kp, int sigcut) {
  extern __shared__ bf16 dynsmem[];
  uint32_t sbase = smem_u32(dynsmem);

  int tid = threadIdx.x;
  int lane = tid & 31, wid = tid >> 5;
  int wm = wid >> 2, wn = wid & 3;  // 2x4 warps, warp tile 64x32

  const bf16* Ab = A + (size_t)(blockIdx.x * BM) * Kp;
  const bf16* Wb = W + (size_t)(blockIdx.y * BN) * Kp;

  // cp.async chunk assignment: 512 chunks per matrix, thread handles 2 each
  int r0 = tid >> 2, c0 = (tid & 3);          // chunk j=0
  int r1 = (tid + 256) >> 2, c1 = (tid & 3);  // chunk j=1

  float acc[4][4][4];
#pragma unroll
  for (int i = 0; i < 4; i++)
#pragma unroll
    for (int j = 0; j < 4; j++)
#pragma unroll
      for (int q = 0; q < 4; q++) acc[i][j][q] = 0.f;

  int KT = Kp / BK;

  // lane base offsets (bytes) inside a stage
  int laneA = (wm * 64 + (lane & 7) + ((lane >> 3) & 1) * 8) * LDSB + ((lane >> 4)) * 16;
  int laneW = BM * LDSB + (wn * 32 + (lane & 7) + (lane >> 4) * 8) * LDSB + (((lane >> 3) & 1)) * 16;

#define ISSUE(stage, kt)                                                            \
  {                                                                                 \
    uint32_t sb = sbase + (stage) * STAGE_BYTES;                                    \
    const bf16* ga = Ab + (size_t)(kt) * BK;                                        \
    const bf16* gw = Wb + (size_t)(kt) * BK;                                        \
    cp16(sb + r0 * LDSB + c0 * 16, ga + (size_t)r0 * Kp + c0 * 8);                  \
    cp16(sb + r1 * LDSB + c1 * 16, ga + (size_t)r1 * Kp + c1 * 8);                  \
    cp16(sb + BM * LDSB + r0 * LDSB + c0 * 16, gw + (size_t)r0 * Kp + c0 * 8);      \
    cp16(sb + BM * LDSB + r1 * LDSB + c1 * 16, gw + (size_t)r1 * Kp + c1 * 8);      \
  }

  ISSUE(0, 0); cp_commit();
  ISSUE(1, 1); cp_commit();

  for (int kt = 0; kt < KT; kt++) {
    cp_wait<1>();
    __syncthreads();
    int st = kt % NST;
    if (kt + 2 < KT) { ISSUE((kt + 2) % NST, kt + 2); }
    cp_commit();

    uint32_t stA = sbase + st * STAGE_BYTES + laneA;
    uint32_t stW = sbase + st * STAGE_BYTES + laneW;
#pragma unroll
    for (int kk = 0; kk < 2; kk++) {
      uint32_t b[8];
      ldm_x4(b, stW + kk * 32);
      ldm_x4(b + 4, stW + 16 * LDSB + kk * 32);
#pragma unroll
      for (int mt = 0; mt < 4; mt++) {
        uint32_t a[4];
        ldm_x4(a, stA + mt * 16 * LDSB + kk * 32);
#pragma unroll
        for (int nt = 0; nt < 4; nt++) mma16816(acc[mt][nt], a, b + nt * 2);
      }
    }
  }
#undef ISSUE

  // epilogue
#pragma unroll
  for (int mt = 0; mt < 4; mt++) {
#pragma unroll
    for (int nt = 0; nt < 4; nt++) {
      int gr = blockIdx.x * BM + wm * 64 + mt * 16 + (lane >> 2);
      int gc = blockIdx.y * BN + wn * 32 + nt * 8 + ((lane & 3) << 1);
#pragma unroll
      for (int half = 0; half < 2; half++) {
        size_t off = (size_t)(gr + half * 8) * M + gc;
        float v0 = acc[mt][nt][half * 2 + 0];
        float v1 = acc[mt][nt][half * 2 + 1];
        if (MODE == 1) {
          if (gc < sigcut) {
            v0 = 1.f / (1.f + expf(-v0));
            v1 = 1.f / (1.f + expf(-v1));
          }
        } else if (MODE == 2) {
          float2 old = *(const float2*)&C[off];
          v0 += old.x; v1 += old.y;
        }
        float2 o2 = {v0, v1};
        *(float2*)&C[off] = o2;
      }
    }
  }
}

// ---------------- LayerNorm (fp32 in -> bf16x3 A-layout out) ----------------
__device__ __forceinline__ void ln_stats(const float* __restrict__ x, float& mean,
                                         float& rstd) {
  int tid = threadIdx.x;
  float s = 0.f, ss = 0.f;
  for (int i = tid; i < kD; i += 256) { float v = x[i]; s += v; ss += v * v; }
  __shared__ float shs[32], shss[32];
  for (int off = 16; off; off >>= 1) {
    s += __shfl_down_sync(0xffffffffu, s, off);
    ss += __shfl_down_sync(0xffffffffu, ss, off);
  }
  if ((tid & 31) == 0) { shs[tid >> 5] = s; shss[tid >> 5] = ss; }
  __syncthreads();
  if (tid < 32) {
    s = tid < 8 ? shs[tid] : 0.f;
    ss = tid < 8 ? shss[tid] : 0.f;
    for (int off = 4; off; off >>= 1) {
      s += __shfl_down_sync(0xffffffffu, s, off);
      ss += __shfl_down_sync(0xffffffffu, ss, off);
    }
    if (tid == 0) { shs[0] = s; shss[0] = ss; }
  }
  __syncthreads();
  mean = shs[0] / (float)kD;
  float var = shss[0] / (float)kD - mean * mean;
  rstd = rsqrtf(var + 1e-5f);
}

__global__ void ln_rows3(const float* __restrict__ in, bf16* __restrict__ out3,
                         const float* __restrict__ w, const float* __restrict__ bb) {
  size_t row = blockIdx.x;
  const float* x = in + row * kD;
  float mean, rstd;
  ln_stats(x, mean, rstd);
  bf16* ob = out3 + row * (3 * kD);
  for (int i = threadIdx.x; i < kD; i += 256) {
    float y = (x[i] - mean) * rstd * w[i] + bb[i];
    bf16 h, l;
    split_bf16(y, h, l);
    ob[i] = h; ob[kD + i] = l; ob[2 * kD + i] = h;
  }
}

__global__ void embed_ln(const int* __restrict__ idx, const float* __restrict__ embed,
                         const float* __restrict__ w, const float* __restrict__ bb,
                         float* __restrict__ out) {
  size_t row = blockIdx.x;
  const float* x = embed + (size_t)idx[row] * kD;
  float mean, rstd;
  ln_stats(x, mean, rstd);
  float* o = out + row * kD;
  for (int i = threadIdx.x; i < kD; i += 256)
    o[i] = (x[i] - mean) * rstd * w[i] + bb[i];
}

// ---------------- TimeMix decay scan ----------------
#define TMCH 16
__global__ void timemix2(const float* __restrict__ rkv, const float* __restrict__ decay_l,
                         float* __restrict__ out) {
  int b = blockIdx.x / (kD / 32);
  int dg = blockIdx.x % (kD / 32);
  int d = dg * 32 + threadIdx.x;
  int chunk = threadIdx.y;
  const int clen = kT / TMCH;
  int t0 = chunk * clen;

  float dec = 1.f / (1.f + expf(-decay_l[d]));
  float logdec = logf(fmaxf(dec, 1e-7f));
  size_t base = (size_t)b * kT * 3 * kD;
  const float* rp = rkv + base + d;
  const float* kp = rkv + base + kD + d;
  const float* vp = rkv + base + 2 * kD + d;
  float* op = out + (size_t)b * kT * kD + d;

  float s = 0.f;
  for (int t = t0; t < t0 + clen; t++) {
    float scale = expf((float)t * logdec);
    float denom = fmaxf(scale, 1e-10f);
    s += kp[(size_t)t * 3 * kD] * vp[(size_t)t * 3 * kD] / denom;
  }
  __shared__ float cs[TMCH][32];
  cs[chunk][threadIdx.x] = s;
  __syncthreads();
  float cum = 0.f;
  for (int c = 0; c < chunk; c++) cum += cs[c][threadIdx.x];
  for (int t = t0; t < t0 + clen; t++) {
    float scale = expf((float)t * logdec);
    float denom = fmaxf(scale, 1e-10f);
    cum += kp[(size_t)t * 3 * kD] * vp[(size_t)t * 3 * kD] / denom;
    op[(size_t)t * kD] = rp[(size_t)t * 3 * kD] * (cum * scale);
  }
}

// ---------------- GroupNorm(1,D) over (T,D) per batch ----------------
__global__ void gn_zero() {
  if (threadIdx.x < kB) { g_gn_sum[threadIdx.x] = 0.0; g_gn_sumsq[threadIdx.x] = 0.0; }
}

__global__ void gn_reduce(const float* __restrict__ in) {
  const int CH = 64;
  int b = blockIdx.x / CH, chunk = blockIdx.x % CH;
  const int n = kT * kD / CH;
  const float* p = in + (size_t)b * kT * kD + (size_t)chunk * n;
  double s = 0.0, ss = 0.0;
  for (int i = threadIdx.x; i < n; i += blockDim.x) {
    double v = (double)p[i];
    s += v; ss += v * v;
  }
  __shared__ double sh1[32], sh2[32];
  for (int off = 16; off; off >>= 1) {
    s += __shfl_down_sync(0xffffffffu, s, off);
    ss += __shfl_down_sync(0xffffffffu, ss, off);
  }
  int tid = threadIdx.x;
  if ((tid & 31) == 0) { sh1[tid >> 5] = s; sh2[tid >> 5] = ss; }
  __syncthreads();
  int nw = (blockDim.x + 31) >> 5;
  if (tid < 32) {
    s = tid < nw ? sh1[tid] : 0.0;
    ss = tid < nw ? sh2[tid] : 0.0;
    for (int off = 16; off; off >>= 1) {
      s += __shfl_down_sync(0xffffffffu, s, off);
      ss += __shfl_down_sync(0xffffffffu, ss, off);
    }
    if (tid == 0) { atomicAdd(&g_gn_sum[b], s); atomicAdd(&g_gn_sumsq[b], ss); }
  }
}

__global__ void gn_apply3(const float* __restrict__ in, const float* __restrict__ gw,
                          const float* __restrict__ gb, bf16* __restrict__ out3) {
  int b = blockIdx.y;
  int idx = blockIdx.x * blockDim.x + threadIdx.x;  // over T*D
  double inv = 1.0 / (double)(kT * kD);
  double m = g_gn_sum[b] * inv;
  double var = g_gn_sumsq[b] * inv - m * m;
  float rstd = rsqrtf((float)var + 1e-5f);
  float mf = (float)m;
  int d = idx & (kD - 1);
  size_t row = (size_t)b * kT + (idx >> 10);
  float y = (in[(size_t)b * kT * kD + idx] - mf) * rstd * gw[d] + gb[d];
  bf16 h, l;
  split_bf16(y, h, l);
  bf16* ob = out3 + row * (3 * kD);
  ob[d] = h; ob[kD + d] = l; ob[2 * kD + d] = h;
}

// ---------------- SwiGLU: ff12 fp32 -> ff3 bf16 A-layout ----------------
__global__ void silu_mul3(const float* __restrict__ ff12, bf16* __restrict__ ff3) {
  size_t i = (size_t)blockIdx.x * blockDim.x + threadIdx.x;  // over N*DFF
  size_t row = i >> 12;          // /4096
  int c = (int)(i & (kDFF - 1));
  float a = ff12[row * (2 * kDFF) + c];
  float b2 = ff12[row * (2 * kDFF) + kDFF + c];
  float y = (a / (1.f + expf(-a))) * b2;
  bf16 h, l;
  split_bf16(y, h, l);
  bf16* ob = ff3 + row * (3 * kDFF);
  ob[c] = h; ob[kDFF + c] = l; ob[2 * kDFF + c] = h;
}

// ---------------- per-row logit stats ----------------
__global__ void rowstats(const float* __restrict__ logits, const int* __restrict__ targets,
                         float* __restrict__ lse, float* __restrict__ tgt,
                         int* __restrict__ amax, float* __restrict__ ent) {
  int row = blockIdx.x;
  const float* Lp = logits + (size_t)row * kV;
  int tid = threadIdx.x;
  __shared__ float svals[256];
  __shared__ int sidx[256];
  float m = -3.4e38f; int mi = 0;
  for (int i = tid; i < kV; i += 256) {
    float v = Lp[i];
    if (v > m) { m = v; mi = i; }
  }
  svals[tid] = m; sidx[tid] = mi;
  __syncthreads();
  for (int off = 128; off > 0; off >>= 1) {
    if (tid < off) {
      float v2 = svals[tid + off]; int i2 = sidx[tid + off];
      if (v2 > svals[tid] || (v2 == svals[tid] && i2 < sidx[tid])) { svals[tid] = v2; sidx[tid] = i2; }
    }
    __syncthreads();
  }
  float M = svals[0]; int MI = sidx[0];
  __syncthreads();
  float s = 0.f, t2 = 0.f;
  for (int i = tid; i < kV; i += 256) {
    float v = Lp[i] - M;
    float e = expf(v);
    s += e; t2 += e * v;
  }
  svals[tid] = s; __syncthreads();
  for (int off = 128; off > 0; off >>= 1) { if (tid < off) svals[tid] += svals[tid + off]; __syncthreads(); }
  float S = svals[0]; __syncthreads();
  svals[tid] = t2; __syncthreads();
  for (int off = 128; off > 0; off >>= 1) { if (tid < off) svals[tid] += svals[tid + off]; __syncthreads(); }
  float T2 = svals[0];
  if (tid == 0) {
    lse[row] = M + logf(S);
    if (ent) ent[row] = logf(S) - T2 / S;
    amax[row] = MI;
    tgt[row] = Lp[targets[row]];
  }
}

// ---------------- exit gate ----------------
__global__ void colmean3(const bf16* __restrict__ he3, float* __restrict__ hbar) {
  int d = blockIdx.x * blockDim.x + threadIdx.x;
  int b = blockIdx.y;
  float s = 0.f;
  const bf16* p = he3 + (size_t)b * kT * (3 * kD);
  for (int t = 0; t < kT; t++) {
    size_t o = (size_t)t * (3 * kD);
    s += __bfloat162float(p[o + d]) + __bfloat162float(p[o + kD + d]);
  }
  hbar[b * kD + d] = s / (float)kT;
}

__global__ void gate_kernel(const float* __restrict__ hbar, const float* __restrict__ w1,
                            const float* __restrict__ b1, const float* __restrict__ w2,
                            const float* __restrict__ b2, int j) {
  __shared__ float g[kB][64];
  int tid = threadIdx.x;
  if (tid < kB * 64) {
    int b = tid / 64, u = tid % 64;
    float s = 0.f;
    const float* hp = hbar + b * kD;
    const float* wp = w1 + (size_t)u * kD;
    for (int d = 0; d < kD; d++) s += hp[d] * wp[d];
    g[b][u] = fmaxf(s + b1[u], 0.f);
  }
  __syncthreads();
  if (tid < kB) {
    float s = 0.f;
    for (int u = 0; u < 64; u++) s += g[tid][u] * w2[u];
    g_conf[j * kB + tid] = 1.f / (1.f + expf(-(s + b2[0])));
  }
}

// ---------------- loss assembly ----------------
__global__ void loss_kernel(float* __restrict__ loss_out) {
  int tid = threadIdx.x;
  float ce_f = 0.f, ce_e[2] = {0.f, 0.f};
  float ag[2][2] = {{0.f, 0.f}, {0.f, 0.f}};
  float oc[2] = {0.f, 0.f};
  const float maxent = logf((float)kV);
  for (int r = tid; r < kN; r += 256) {
    int fp = g_amax_f[r];
    ce_f += g_lse_f[r] - g_tgt_f[r];
    int b = r / kT;
#pragma unroll
    for (int j = 0; j < 2; j++) {
      ce_e[j] += g_lse_e[j * kN + r] - g_tgt_e[j * kN + r];
      int ep = g_amax_e[j * kN + r];
      if (ep == fp) ag[j][b] += 1.f;
      else oc[j] += (1.f - g_ent_e[j * kN + r] / maxent);
    }
  }
  __shared__ float sh[256];
  float vals[9] = {ce_f, ce_e[0], ce_e[1], ag[0][0], ag[0][1], ag[1][0], ag[1][1], oc[0], oc[1]};
  float red[9];
#pragma unroll
  for (int q = 0; q < 9; q++) {
    sh[tid] = vals[q];
    __syncthreads();
    for (int off = 128; off > 0; off >>= 1) { if (tid < off) sh[tid] += sh[tid + off]; __syncthreads(); }
    red[q] = sh[0];
    __syncthreads();
  }
  if (tid == 0) {
    const float w[2] = {0.3f, 0.5f};
    float loss = red[0] / (float)kN;
    for (int j = 0; j < 2; j++) {
      loss += w[j] * (red[1 + j] / (float)kN);
      float bce = 0.f;
      for (int b = 0; b < kB; b++) {
        float agree = red[3 + j * 2 + b] / (float)kT;
        float c = fminf(fmaxf(g_conf[j * kB + b], 1e-7f), 1.f - 1e-7f);
        bce += -(agree * logf(c) + (1.f - agree) * logf(1.f - c));
      }
      loss += 0.5f * (bce / (float)kB);
      loss += 0.1f * (red[7 + j] / (float)kN);
    }
    loss_out[0] = loss;
  }
}

// ---------------- host orchestration ----------------
#define DSMEM (NST * STAGE_BYTES)

extern "C" void kernel_launch(void* const* d_in, const int* in_sizes, int n_in,
                              void* d_out, int out_size) {
  const int* idx = (const int*)d_in[0];
  const int* targets = (const int*)d_in[1];
  const float* embed = (const float*)d_in[2];
  const float* ln_in_w = (const float*)d_in[3];
  const float* ln_in_b = (const float*)d_in[4];
  const float* Wr = (const float*)d_in[5];
  const float* Wk = (const float*)d_in[6];
  const float* Wv = (const float*)d_in[7];
  const float* Wo_tm = (const float*)d_in[8];
  const float* decay = (const float*)d_in[9];
  const float* gn_w = (const float*)d_in[10];
  const float* gn_b = (const float*)d_in[11];
  const float* ln1_w = (const float*)d_in[12];
  const float* ln1_b = (const float*)d_in[13];
  const float* ln2_w = (const float*)d_in[14];
  const float* ln2_b = (const float*)d_in[15];
  const float* W1 = (const float*)d_in[16];
  const float* W2 = (const float*)d_in[17];
  const float* Wo_cm = (const float*)d_in[18];
  const float* ln_out_w = (const float*)d_in[19];
  const float* ln_out_b = (const float*)d_in[20];
  const float* exit_ln_w = (const float*)d_in[21];
  const float* exit_ln_b = (const float*)d_in[22];
  const float* exit_head = (const float*)d_in[23];
  const float* gate_w1 = (const float*)d_in[24];
  const float* gate_b1 = (const float*)d_in[25];
  const float* gate_w2 = (const float*)d_in[26];
  const float* gate_b2 = (const float*)d_in[27];
  float* out = (float*)d_out;

  float *xp, *rkvp, *attp, *ff12p, *elp, *hbarp;
  float *lse_f, *tgt_f, *lse_e, *tgt_e, *ent_e;
  int *amax_f, *amax_e;
  bf16 *h3p, *ff3p, *Wrkv3, *Wotm3, *W123, *Wocm3, *embed3, *exit3;
  cudaGetSymbolAddress((void**)&xp, g_x);
  cudaGetSymbolAddress((void**)&rkvp, g_rkv);
  cudaGetSymbolAddress((void**)&attp, g_att);
  cudaGetSymbolAddress((void**)&ff12p, g_ff12);
  cudaGetSymbolAddress((void**)&elp, g_elog);
  cudaGetSymbolAddress((void**)&hbarp, g_hbar);
  cudaGetSymbolAddress((void**)&lse_f, g_lse_f);
  cudaGetSymbolAddress((void**)&tgt_f, g_tgt_f);
  cudaGetSymbolAddress((void**)&amax_f, g_amax_f);
  cudaGetSymbolAddress((void**)&lse_e, g_lse_e);
  cudaGetSymbolAddress((void**)&tgt_e, g_tgt_e);
  cudaGetSymbolAddress((void**)&ent_e, g_ent_e);
  cudaGetSymbolAddress((void**)&amax_e, g_amax_e);
  cudaGetSymbolAddress((void**)&h3p, g_h3);
  cudaGetSymbolAddress((void**)&ff3p, g_ff3);
  cudaGetSymbolAddress((void**)&Wrkv3, g_Wrkv3);
  cudaGetSymbolAddress((void**)&Wotm3, g_Wotm3);
  cudaGetSymbolAddress((void**)&W123, g_W123);
  cudaGetSymbolAddress((void**)&Wocm3, g_Wocm3);
  cudaGetSymbolAddress((void**)&embed3, g_embed3);
  cudaGetSymbolAddress((void**)&exit3, g_exit3);

  cudaFuncSetAttribute(gemm3<0>, cudaFuncAttributeMaxDynamicSharedMemorySize, DSMEM);
  cudaFuncSetAttribute(gemm3<1>, cudaFuncAttributeMaxDynamicSharedMemorySize, DSMEM);
  cudaFuncSetAttribute(gemm3<2>, cudaFuncAttributeMaxDynamicSharedMemorySize, DSMEM);

  // ---- weight conversions ----
  {
    long t4;
    t4 = (long)kL * kD * kD / 4;  // 3.1M
    conv3w<<<(unsigned)((t4 + 255) / 256), 256>>>(Wr, Wrkv3, kD, t4, kD, 3 * kD, 0);
    conv3w<<<(unsigned)((t4 + 255) / 256), 256>>>(Wk, Wrkv3, kD, t4, kD, 3 * kD, kD);
    conv3w<<<(unsigned)((t4 + 255) / 256), 256>>>(Wv, Wrkv3, kD, t4, kD, 3 * kD, 2 * kD);
    conv3w<<<(unsigned)((t4 + 255) / 256), 256>>>(Wo_tm, Wotm3, kD, t4, kL * kD, kL * kD, 0);
    t4 = (long)kL * kDFF * kD / 4;  // 12.6M
    conv3w<<<(unsigned)((t4 + 255) / 256), 256>>>(W1, W123, kD, t4, kDFF, 2 * kDFF, 0);
    conv3w<<<(unsigned)((t4 + 255) / 256), 256>>>(W2, W123, kD, t4, kDFF, 2 * kDFF, kDFF);
    t4 = (long)kL * kD * kDFF / 4;
    conv3w<<<(unsigned)((t4 + 255) / 256), 256>>>(Wo_cm, Wocm3, kDFF, t4, kL * kD, kL * kD, 0);
    t4 = (long)kV * kD / 4;  // 8.2M
    conv3w<<<(unsigned)((t4 + 255) / 256), 256>>>(embed, embed3, kD, t4, kV, kV, 0);
    t4 = 2L * kV * kD / 4;  // 16.4M
    conv3w<<<(unsigned)((t4 + 255) / 256), 256>>>(exit_head, exit3, kD, t4, 2 * kV, 2 * kV, 0);
  }

  dim3 g_rkvg(kN / BM, (3 * kD) / BN);   // (16,24)
  dim3 g_dd(kN / BM, kD / BN);           // (16,8)
  dim3 g_w12(kN / BM, (2 * kDFF) / BN);  // (16,64)
  dim3 g_vg(kN / BM, kV / BN);           // (16,250)

  embed_ln<<<kN, 256>>>(idx, embed, ln_in_w, ln_in_b, xp);

  for (int i = 0; i < kL; i++) {
    // --- TimeMix ---
    ln_rows3<<<kN, 256>>>(xp, h3p, ln1_w + i * kD, ln1_b + i * kD);
    gemm3<1><<<g_rkvg, 256, DSMEM>>>(h3p, Wrkv3 + (size_t)i * 3 * kD * 3 * kD, rkvp,
                                     3 * kD, 3 * kD, kD);
    timemix2<<<kB * (kD / 32), dim3(32, TMCH)>>>(rkvp, decay + i * kD, attp);
    gn_zero<<<1, 32>>>();
    gn_reduce<<<kB * 64, 256>>>(attp);
    gn_apply3<<<dim3(kT * kD / 256, kB), 256>>>(attp, gn_w + i * kD, gn_b + i * kD, h3p);
    gemm3<2><<<g_dd, 256, DSMEM>>>(h3p, Wotm3 + (size_t)i * kD * 3 * kD, xp, kD, 3 * kD, 0);
    // --- ChannelMix ---
    ln_rows3<<<kN, 256>>>(xp, h3p, ln2_w + i * kD, ln2_b + i * kD);
    gemm3<0><<<g_w12, 256, DSMEM>>>(h3p, W123 + (size_t)i * 2 * kDFF * 3 * kD, ff12p,
                                    2 * kDFF, 3 * kD, 0);
    silu_mul3<<<(kN * kDFF) / 256, 256>>>(ff12p, ff3p);
    gemm3<2><<<g_dd, 256, DSMEM>>>(ff3p, Wocm3 + (size_t)i * kD * 3 * kDFF, xp,
                                   kD, 3 * kDFF, 0);
    // --- early exits ---
    if (i == 3 || i == 7) {
      int j = (i == 3) ? 0 : 1;
      ln_rows3<<<kN, 256>>>(xp, h3p, exit_ln_w + j * kD, exit_ln_b + j * kD);
      gemm3<0><<<g_vg, 256, DSMEM>>>(h3p, exit3 + (size_t)j * kV * 3 * kD, elp,
                                     kV, 3 * kD, 0);
      rowstats<<<kN, 256>>>(elp, targets, lse_e + j * kN, tgt_e + j * kN,
                            amax_e + j * kN, ent_e + j * kN);
      colmean3<<<dim3(kD / 256, kB), 256>>>(h3p, hbarp);
      gate_kernel<<<1, 128>>>(hbarp, gate_w1 + (size_t)j * 64 * kD, gate_b1 + j * 64,
                              gate_w2 + j * 64, gate_b2 + j, j);
    }
  }

  // final LN + tied head into d_out
  ln_rows3<<<kN, 256>>>(xp, h3p, ln_out_w, ln_out_b);
  gemm3<0><<<g_vg, 256, DSMEM>>>(h3p, embed3, out, kV, 3 * kD, 0);
  rowstats<<<kN, 256>>>(out, targets, lse_f, tgt_f, amax_f, (float*)nullptr);
  loss_kernel<<<1, 256>>>(out + (size_t)kN * kV);
}